// round 9
// baseline (speedup 1.0000x reference)
#include <cuda_runtime.h>
#include <math.h>

#define T_LEN 128
#define F_DIM 16
#define ST 129   // t-stride of feature-major shared buffers (any non-mult-of-4 ok)

// Operator parameters (lap is block-tridiagonal; fully described by these):
__device__ float g_Mi[256];   // interior diagonal block of lap (16x16), row-major M[f][g]
__device__ float g_Mb[256];   // boundary diagonal block (t=0,127)
__device__ float g_eii[16];   // interior-interior temporal coupling (diag 16-vec)
__device__ float g_ebi[16];   // boundary-interior temporal coupling
__device__ float g_c;         // 2 / sigma_max(lap)

// ---------------------------------------------------------------------------
// Kernel 1 (analytic, warp-parallel): sigma_max(L) via modal decomposition.
// sigma(L0) = union_k sigma(Mi + lam_k Eii); sigma_max convex in lam => max at
// lam = +/- 2cos(pi/129). One warp: 2 halves x 16 components; exact 16-step
// Lanczos on B = A^T A; grid Sturm bisection. (Frozen from R8: rel_err at floor.)
// ---------------------------------------------------------------------------
__global__ void __launch_bounds__(128) setup_analytic_kernel(const float* __restrict__ adj) {
    __shared__ float sAhat[16][16];
    __shared__ float sMi[16][16], sMiT[16][16];
    __shared__ float seii[16];
    __shared__ float spb[16], spi[16];

    const int tid = threadIdx.x;

    for (int i = tid; i < 256; i += 128) {
        int f = i >> 4, g = i & 15;
        sAhat[f][g] = (f == g) ? 1.0f : 1.0f / (1.0f + expf(-adj[i]));
    }
    __syncthreads();

    if (tid < 16) {
        float a = 0.0f;
        #pragma unroll
        for (int g = 0; g < 16; g++) a += sAhat[tid][g];
        spb[tid] = rsqrtf(a + 1.0f);
        spi[tid] = rsqrtf(a + 2.0f);
    }
    __syncthreads();

    for (int i = tid; i < 256; i += 128) {
        int f = i >> 4, g = i & 15;
        float diag = (f == g) ? 1.0f : 0.0f;
        float mi = diag - spi[f] * sAhat[f][g] * spi[g];
        float mb = diag - spb[f] * sAhat[f][g] * spb[g];
        sMi[f][g] = mi;  sMiT[g][f] = mi;
        g_Mi[i] = mi;    g_Mb[i] = mb;
    }
    if (tid < 16) {
        seii[tid] = -spi[tid] * spi[tid];
        g_eii[tid] = seii[tid];
        g_ebi[tid] = -spb[tid] * spi[tid];
    }
    __syncthreads();

    if (tid >= 32) return;

    const int lane = tid;
    const int half = lane >> 4;
    const int f    = lane & 15;
    const int base = half << 4;
    const float lam = (half ? -2.0f : 2.0f) * cosf(3.14159265358979f / 129.0f);

    float Mr[16], Tr[16];
    #pragma unroll
    for (int g = 0; g < 16; g++) { Mr[g] = sMi[f][g]; Tr[g] = sMiT[f][g]; }
    const float le = lam * seii[f];

    float v, vp = 0.0f;
    {
        unsigned h = (unsigned)(f * 2654435761u) + 0x9E3779B9u;
        h ^= h >> 15; h *= 0x2C1B3C6Du; h ^= h >> 12; h *= 0x297A2D39u; h ^= h >> 15;
        v = (float)(h & 0xFFFFFFu) * (1.0f / 16777216.0f) - 0.5f + 0.03f * (float)f;
        float nn = v * v;
        #pragma unroll
        for (int o = 8; o > 0; o >>= 1) nn += __shfl_xor_sync(0xFFFFFFFFu, nn, o);
        v *= rsqrtf(nn);
    }

    float al[16], be[16];
    float bprev = 0.0f;
    #pragma unroll
    for (int it = 0; it < 16; it++) {
        float a = le * v;
        #pragma unroll
        for (int g = 0; g < 16; g++)
            a += Mr[g] * __shfl_sync(0xFFFFFFFFu, v, base + g);
        float w = le * a;
        #pragma unroll
        for (int g = 0; g < 16; g++)
            w += Tr[g] * __shfl_sync(0xFFFFFFFFu, a, base + g);
        float pa = v * w;
        #pragma unroll
        for (int o = 8; o > 0; o >>= 1) pa += __shfl_xor_sync(0xFFFFFFFFu, pa, o);
        float alpha = pa;
        w -= alpha * v + bprev * vp;
        float ps = w * w;
        #pragma unroll
        for (int o = 8; o > 0; o >>= 1) ps += __shfl_xor_sync(0xFFFFFFFFu, ps, o);
        float beta = sqrtf(ps);
        al[it] = alpha; be[it] = beta;
        float rb = (beta > 1e-30f) ? 1.0f / beta : 0.0f;
        vp = v; v = w * rb;
        bprev = beta;
    }

    float lo = 0.0f, hi = 8.0f;
    for (int r = 0; r < 6; r++) {
        float x = lo + (hi - lo) * (float)(f + 1) * (1.0f / 17.0f);
        int cnt = 0;
        float d = al[0] - x;
        if (d < 0.0f) cnt++;
        #pragma unroll
        for (int i = 1; i < 16; i++) {
            float dd = (fabsf(d) < 1e-25f) ? ((d < 0.0f) ? -1e-25f : 1e-25f) : d;
            d = (al[i] - x) - (be[i - 1] * be[i - 1]) / dd;
            if (d < 0.0f) cnt++;
        }
        bool ge = (cnt < 16);
        unsigned m = (__ballot_sync(0xFFFFFFFFu, ge) >> (half << 4)) & 0xFFFFu;
        int nge = __popc(m);
        float w17 = (hi - lo) * (1.0f / 17.0f);
        float nlo = lo + w17 * (float)nge;
        float nhi = lo + w17 * (float)(nge + 1);
        lo = nlo; hi = nhi;
    }
    float lmax = 0.5f * (lo + hi);

    float other = __shfl_sync(0xFFFFFFFFu, lmax, lane ^ 16);
    lmax = fmaxf(lmax, other);
    if (lane == 0) g_c = 2.0f / sqrtf(lmax);
}

// ---------------------------------------------------------------------------
// Kernel 2 (v3): 256 threads/block, one batch row per block.
// Warps 0-3: h=0 (features 0-7), warps 4-7: h=1 (features 8-15); t = tid&127.
// Feature-major shared tiles [16][ST]: all per-t vector reads are stride-1
// scalar LDS (conflict-free); matrix/weight rows are warp-uniform broadcasts.
// y1 = L_s^T y0, y2 = 2 L_s^T y1 - y0, out = y0 W0 + y1 W1 + y2 W2 + bias.
// Output GEMM split by f-half with partner-partial exchange through shared.
// ---------------------------------------------------------------------------
__global__ void __launch_bounds__(256) sgconv_main_kernel(
    const float* __restrict__ x, const float* __restrict__ weight,
    const float* __restrict__ bias, float* __restrict__ out) {
    __shared__ float sAiT[16][16], sAbT[16][16];   // (c*M - I)^T rows
    __shared__ float scei[16], sceb[16];
    __shared__ float sW0[16][16], sW1[16][16], sW2[16][16];
    __shared__ float sbias[16];
    __shared__ float xF[16][ST];    // feature-major x
    __shared__ float y1F[16][ST];   // feature-major y1
    __shared__ float pvF[16][ST];   // partial-output exchange [o][t]

    const int tid = threadIdx.x;
    const int t   = tid & 127;
    const int h   = tid >> 7;       // 0: features 0-7, 1: features 8-15
    const int fb  = h << 3;
    const float c = g_c;

    // param init (256 threads, one element each)
    {
        int i = tid;
        int f = i >> 4, g = i & 15;
        float diag = (f == g) ? 1.0f : 0.0f;
        sAiT[g][f] = c * g_Mi[i] - diag;   // transposed store
        sAbT[g][f] = c * g_Mb[i] - diag;
        sW0[f][g] = weight[i];
        sW1[f][g] = weight[256 + i];
        sW2[f][g] = weight[512 + i];
        if (i < 16) {
            scei[i] = c * g_eii[i];
            sceb[i] = c * g_ebi[i];
            sbias[i] = bias[i];
        }
    }

    const bool bnd = (t == 0 || t == 127);

    // load my 8 features of x[b, t, :] (2 float4, stride-64B across lanes)
    float y0h[8];
    {
        const float4* xb = (const float4*)(x + (size_t)blockIdx.x * 2048 + t * 16 + fb);
        float4 v0 = xb[0], v1 = xb[1];
        y0h[0] = v0.x; y0h[1] = v0.y; y0h[2] = v0.z; y0h[3] = v0.w;
        y0h[4] = v1.x; y0h[5] = v1.y; y0h[6] = v1.z; y0h[7] = v1.w;
        #pragma unroll
        for (int j = 0; j < 8; j++) xF[fb + j][t] = y0h[j];
    }
    __syncthreads();   // params + xF visible

    // cache edge coefficients for my features (t-class fixed per thread)
    float el8[8], er8[8];
    {
        const float* el = (t == 1 || t == 127) ? sceb : scei;
        const float* er = (t == 0 || t == 126) ? sceb : scei;
        #pragma unroll
        for (int j = 0; j < 8; j++) { el8[j] = el[fb + j]; er8[j] = er[fb + j]; }
    }

    // structured apply for my 8 features, reading feature-major buffer B
    auto apply_half = [&](float (&B)[16][ST], const float* ownh, float* DST) {
        // assemble full src vector at own t (own half from regs, other from shared)
        float src[16];
        if (h == 0) {
            #pragma unroll
            for (int j = 0; j < 8; j++) { src[j] = ownh[j]; src[8 + j] = B[8 + j][t]; }
        } else {
            #pragma unroll
            for (int j = 0; j < 8; j++) { src[j] = B[j][t]; src[8 + j] = ownh[j]; }
        }
        #pragma unroll
        for (int j = 0; j < 8; j++) {
            int f = fb + j;
            const float4* R = (const float4*)(bnd ? &sAbT[f][0] : &sAiT[f][0]);
            float4 m0 = R[0], m1 = R[1], m2 = R[2], m3 = R[3];
            float acc =
                  (m0.x*src[0]  + m0.y*src[1]  + m0.z*src[2]  + m0.w*src[3])
                + (m1.x*src[4]  + m1.y*src[5]  + m1.z*src[6]  + m1.w*src[7])
                + (m2.x*src[8]  + m2.y*src[9]  + m2.z*src[10] + m2.w*src[11])
                + (m3.x*src[12] + m3.y*src[13] + m3.z*src[14] + m3.w*src[15]);
            if (t > 0)   acc += el8[j] * B[f][t - 1];
            if (t < 127) acc += er8[j] * B[f][t + 1];
            DST[j] = acc;
        }
    };

    // y1 (my half)
    float y1h[8];
    apply_half(xF, y0h, y1h);
    #pragma unroll
    for (int j = 0; j < 8; j++) y1F[fb + j][t] = y1h[j];
    __syncthreads();

    // y2 = 2 * apply(y1) - y0 (my half)
    float y2h[8];
    apply_half(y1F, y1h, y2h);
    #pragma unroll
    for (int j = 0; j < 8; j++) y2h[j] = 2.0f * y2h[j] - y0h[j];

    // output GEMM, o-chunked: first the partner's o-half (publish), then mine.
    const int ob_other = (1 - h) << 3;
    const int ob_mine  = fb;
    float povA[8];   // partials for partner's o-half
    #pragma unroll
    for (int k = 0; k < 8; k++) povA[k] = 0.0f;
    #pragma unroll
    for (int j = 0; j < 8; j++) {
        int f = fb + j;
        float a0 = y0h[j], a1 = y1h[j], a2 = y2h[j];
        const float4* W0r = (const float4*)&sW0[f][ob_other];
        const float4* W1r = (const float4*)&sW1[f][ob_other];
        const float4* W2r = (const float4*)&sW2[f][ob_other];
        float4 w00 = W0r[0], w01 = W0r[1];
        float4 w10 = W1r[0], w11 = W1r[1];
        float4 w20 = W2r[0], w21 = W2r[1];
        povA[0] += a0*w00.x + a1*w10.x + a2*w20.x;
        povA[1] += a0*w00.y + a1*w10.y + a2*w20.y;
        povA[2] += a0*w00.z + a1*w10.z + a2*w20.z;
        povA[3] += a0*w00.w + a1*w10.w + a2*w20.w;
        povA[4] += a0*w01.x + a1*w11.x + a2*w21.x;
        povA[5] += a0*w01.y + a1*w11.y + a2*w21.y;
        povA[6] += a0*w01.z + a1*w11.z + a2*w21.z;
        povA[7] += a0*w01.w + a1*w11.w + a2*w21.w;
    }
    #pragma unroll
    for (int k = 0; k < 8; k++) pvF[ob_other + k][t] = povA[k];

    float povB[8];   // partials for my o-half
    #pragma unroll
    for (int k = 0; k < 8; k++) povB[k] = 0.0f;
    #pragma unroll
    for (int j = 0; j < 8; j++) {
        int f = fb + j;
        float a0 = y0h[j], a1 = y1h[j], a2 = y2h[j];
        const float4* W0r = (const float4*)&sW0[f][ob_mine];
        const float4* W1r = (const float4*)&sW1[f][ob_mine];
        const float4* W2r = (const float4*)&sW2[f][ob_mine];
        float4 w00 = W0r[0], w01 = W0r[1];
        float4 w10 = W1r[0], w11 = W1r[1];
        float4 w20 = W2r[0], w21 = W2r[1];
        povB[0] += a0*w00.x + a1*w10.x + a2*w20.x;
        povB[1] += a0*w00.y + a1*w10.y + a2*w20.y;
        povB[2] += a0*w00.z + a1*w10.z + a2*w20.z;
        povB[3] += a0*w00.w + a1*w10.w + a2*w20.w;
        povB[4] += a0*w01.x + a1*w11.x + a2*w21.x;
        povB[5] += a0*w01.y + a1*w11.y + a2*w21.y;
        povB[6] += a0*w01.z + a1*w11.z + a2*w21.z;
        povB[7] += a0*w01.w + a1*w11.w + a2*w21.w;
    }
    __syncthreads();

    // combine with partner's partial for my o-half, add bias, store
    float ov[8];
    #pragma unroll
    for (int k = 0; k < 8; k++)
        ov[k] = povB[k] + pvF[ob_mine + k][t] + sbias[ob_mine + k];
    float4* ob = (float4*)(out + (size_t)blockIdx.x * 2048 + t * 16 + ob_mine);
    ob[0] = make_float4(ov[0], ov[1], ov[2], ov[3]);
    ob[1] = make_float4(ov[4], ov[5], ov[6], ov[7]);
}

extern "C" void kernel_launch(void* const* d_in, const int* in_sizes, int n_in,
                              void* d_out, int out_size) {
    const float* x      = (const float*)d_in[0];  // [1024,128,16]
    const float* weight = (const float*)d_in[1];  // [3,16,16]
    const float* bias   = (const float*)d_in[2];  // [16]
    const float* adj    = (const float*)d_in[3];  // [16,16]
    int batch = in_sizes[0] / (T_LEN * F_DIM);

    setup_analytic_kernel<<<1, 128>>>(adj);
    sgconv_main_kernel<<<batch, 256>>>(x, weight, bias, (float*)d_out);
}

// round 10
// speedup vs baseline: 1.0127x; 1.0127x over previous
#include <cuda_runtime.h>
#include <math.h>

#define T_LEN 128
#define F_DIM 16

// Operator parameters (written by kernel 1):
__device__ float g_Mi[256];   // interior diagonal block of lap, row-major M[f][g]
__device__ float g_Mb[256];   // boundary diagonal block (t=0,127)
__device__ float g_eii[16];   // interior temporal coupling (diag 16-vec)
__device__ float g_ebi[16];   // boundary temporal coupling
__device__ float g_c;         // 2 / sigma_max(lap)

// Band kernel H (written by kernel 2): [7 classes][5 taps][16 f][16 o]
__device__ __align__(16) float g_H[7 * 5 * 16 * 16];

// ---------------------------------------------------------------------------
// Kernel 1 (frozen from R8): sigma_max(L) via modal decomposition.
// sigma(L0) = union_k sigma(Mi + lam_k Eii); sigma_max convex in lam => max at
// lam = +/- 2cos(pi/129). One warp, 2 halves x 16 comps; exact 16-step Lanczos
// on B = A^T A; grid Sturm bisection. rel_err at fp32 floor (verified R8).
// ---------------------------------------------------------------------------
__global__ void __launch_bounds__(128) setup_analytic_kernel(const float* __restrict__ adj) {
    __shared__ float sAhat[16][16];
    __shared__ float sMi[16][16], sMiT[16][16];
    __shared__ float seii[16];
    __shared__ float spb[16], spi[16];

    const int tid = threadIdx.x;

    for (int i = tid; i < 256; i += 128) {
        int f = i >> 4, g = i & 15;
        sAhat[f][g] = (f == g) ? 1.0f : 1.0f / (1.0f + expf(-adj[i]));
    }
    __syncthreads();

    if (tid < 16) {
        float a = 0.0f;
        #pragma unroll
        for (int g = 0; g < 16; g++) a += sAhat[tid][g];
        spb[tid] = rsqrtf(a + 1.0f);
        spi[tid] = rsqrtf(a + 2.0f);
    }
    __syncthreads();

    for (int i = tid; i < 256; i += 128) {
        int f = i >> 4, g = i & 15;
        float diag = (f == g) ? 1.0f : 0.0f;
        float mi = diag - spi[f] * sAhat[f][g] * spi[g];
        float mb = diag - spb[f] * sAhat[f][g] * spb[g];
        sMi[f][g] = mi;  sMiT[g][f] = mi;
        g_Mi[i] = mi;    g_Mb[i] = mb;
    }
    if (tid < 16) {
        seii[tid] = -spi[tid] * spi[tid];
        g_eii[tid] = seii[tid];
        g_ebi[tid] = -spb[tid] * spi[tid];
    }
    __syncthreads();

    if (tid >= 32) return;

    const int lane = tid;
    const int half = lane >> 4;
    const int f    = lane & 15;
    const int base = half << 4;
    const float lam = (half ? -2.0f : 2.0f) * cosf(3.14159265358979f / 129.0f);

    float Mr[16], Tr[16];
    #pragma unroll
    for (int g = 0; g < 16; g++) { Mr[g] = sMi[f][g]; Tr[g] = sMiT[f][g]; }
    const float le = lam * seii[f];

    float v, vp = 0.0f;
    {
        unsigned h = (unsigned)(f * 2654435761u) + 0x9E3779B9u;
        h ^= h >> 15; h *= 0x2C1B3C6Du; h ^= h >> 12; h *= 0x297A2D39u; h ^= h >> 15;
        v = (float)(h & 0xFFFFFFu) * (1.0f / 16777216.0f) - 0.5f + 0.03f * (float)f;
        float nn = v * v;
        #pragma unroll
        for (int o = 8; o > 0; o >>= 1) nn += __shfl_xor_sync(0xFFFFFFFFu, nn, o);
        v *= rsqrtf(nn);
    }

    float al[16], be[16];
    float bprev = 0.0f;
    #pragma unroll
    for (int it = 0; it < 16; it++) {
        float a = le * v;
        #pragma unroll
        for (int g = 0; g < 16; g++)
            a += Mr[g] * __shfl_sync(0xFFFFFFFFu, v, base + g);
        float w = le * a;
        #pragma unroll
        for (int g = 0; g < 16; g++)
            w += Tr[g] * __shfl_sync(0xFFFFFFFFu, a, base + g);
        float pa = v * w;
        #pragma unroll
        for (int o = 8; o > 0; o >>= 1) pa += __shfl_xor_sync(0xFFFFFFFFu, pa, o);
        float alpha = pa;
        w -= alpha * v + bprev * vp;
        float ps = w * w;
        #pragma unroll
        for (int o = 8; o > 0; o >>= 1) ps += __shfl_xor_sync(0xFFFFFFFFu, ps, o);
        float beta = sqrtf(ps);
        al[it] = alpha; be[it] = beta;
        float rb = (beta > 1e-30f) ? 1.0f / beta : 0.0f;
        vp = v; v = w * rb;
        bprev = beta;
    }

    float lo = 0.0f, hi = 8.0f;
    for (int r = 0; r < 6; r++) {
        float x = lo + (hi - lo) * (float)(f + 1) * (1.0f / 17.0f);
        int cnt = 0;
        float d = al[0] - x;
        if (d < 0.0f) cnt++;
        #pragma unroll
        for (int i = 1; i < 16; i++) {
            float dd = (fabsf(d) < 1e-25f) ? ((d < 0.0f) ? -1e-25f : 1e-25f) : d;
            d = (al[i] - x) - (be[i - 1] * be[i - 1]) / dd;
            if (d < 0.0f) cnt++;
        }
        bool ge = (cnt < 16);
        unsigned m = (__ballot_sync(0xFFFFFFFFu, ge) >> (half << 4)) & 0xFFFFu;
        int nge = __popc(m);
        float w17 = (hi - lo) * (1.0f / 17.0f);
        float nlo = lo + w17 * (float)nge;
        float nhi = lo + w17 * (float)(nge + 1);
        lo = nlo; hi = nhi;
    }
    float lmax = 0.5f * (lo + hi);

    float other = __shfl_sync(0xFFFFFFFFu, lmax, lane ^ 16);
    lmax = fmaxf(lmax, other);
    if (lane == 0) g_c = 2.0f / sqrtf(lmax);
}

// ---------------------------------------------------------------------------
// Kernel 2: build band kernel H by unit-vector probing of the exact pipeline.
// For class rep ts, tap dt, feature f: set x = e_f at time p = ts+dt-2, run
// y1 = Ls^T x (window), y2 = 2 Ls^T y1 - x, H row = y0 W0 + y1 W1 + y2 W2.
// 560 independent tasks over 512 threads.
// ---------------------------------------------------------------------------
__global__ void __launch_bounds__(512) build_H_kernel(const float* __restrict__ weight) {
    __shared__ float AiT[16][16], AbT[16][16];   // AT[r][g] = (c*M - I)^T
    __shared__ float AiC[16][16], AbC[16][16];   // AiC[f][r] = AiT[r][f]
    __shared__ float cei[16], ceb[16];
    __shared__ float W[3][16][16];

    const int tid = threadIdx.x;
    const float c = g_c;

    if (tid < 256) {
        int i = tid;
        int f = i >> 4, g = i & 15;
        float diag = (f == g) ? 1.0f : 0.0f;
        float vi = c * g_Mi[i] - diag;
        float vb = c * g_Mb[i] - diag;
        AiT[g][f] = vi;  AbT[g][f] = vb;   // same as R8's sAiT/sAbT
        AiC[f][g] = vi;  AbC[f][g] = vb;   // column copy: AiC[f][r] = AT[r][f]
        W[0][f][g] = weight[i];
        W[1][f][g] = weight[256 + i];
        W[2][f][g] = weight[512 + i];
        if (i < 16) {
            cei[i] = c * g_eii[i];
            ceb[i] = c * g_ebi[i];
        }
    }
    __syncthreads();

    const int reps[7] = {0, 1, 2, 3, 125, 126, 127};

    for (int task = tid; task < 560; task += 512) {
        const int f    = task & 15;
        const int rest = task >> 4;
        const int dt   = rest % 5;
        const int cls  = rest / 5;
        const int ts   = reps[cls];
        const int p    = ts + dt - 2;

        float Hrow[16];
        if (p < 0 || p > 127) {
            #pragma unroll
            for (int o = 0; o < 16; o++) Hrow[o] = 0.0f;
        } else {
            // y1 on window s = ts-1 .. ts+1
            float y1w[3][16];
            #pragma unroll
            for (int si = 0; si < 3; si++) {
                int s = ts - 1 + si;
                #pragma unroll
                for (int r = 0; r < 16; r++) y1w[si][r] = 0.0f;
                if (s < 0 || s > 127) continue;
                bool sbnd = (s == 0 || s == 127);
                if (s == p) {
                    const float* col = sbnd ? &AbC[f][0] : &AiC[f][0];
                    #pragma unroll
                    for (int r = 0; r < 16; r++) y1w[si][r] = col[r];
                }
                if (s - 1 == p) {
                    const float* el = (s == 1 || s == 127) ? ceb : cei;
                    y1w[si][f] += el[f];
                }
                if (s + 1 == p) {
                    const float* er = (s == 0 || s == 126) ? ceb : cei;
                    y1w[si][f] += er[f];
                }
            }
            // y2 = 2 * (Ls^T y1)[ts] - y0
            bool tb = (ts == 0 || ts == 127);
            float y2[16];
            #pragma unroll
            for (int r = 0; r < 16; r++) {
                const float* AR = tb ? &AbT[r][0] : &AiT[r][0];
                float acc = 0.0f;
                #pragma unroll
                for (int g = 0; g < 16; g++) acc += AR[g] * y1w[1][g];
                if (ts > 0) {
                    const float* el = (ts == 1 || ts == 127) ? ceb : cei;
                    acc += el[r] * y1w[0][r];
                }
                if (ts < 127) {
                    const float* er = (ts == 0 || ts == 126) ? ceb : cei;
                    acc += er[r] * y1w[2][r];
                }
                float y0r = (ts == p && r == f) ? 1.0f : 0.0f;
                y2[r] = 2.0f * acc - y0r;
            }
            // H row over o
            #pragma unroll
            for (int o = 0; o < 16; o++) {
                float h = (ts == p) ? W[0][f][o] : 0.0f;
                #pragma unroll
                for (int r = 0; r < 16; r++)
                    h += y1w[1][r] * W[1][r][o] + y2[r] * W[2][r][o];
                Hrow[o] = h;
            }
        }
        #pragma unroll
        for (int o = 0; o < 16; o++) g_H[task * 16 + o] = Hrow[o];
    }
}

// ---------------------------------------------------------------------------
// Kernel 3: main compute = 5-tap band GEMM. One block per batch row, thread t.
// out[t] = sum_{dt} x[t+dt-2] * H[cls(t)][dt] + bias. x zero-padded by 2 rows
// at each end (branchless); single barrier; H broadcast from shared.
// ---------------------------------------------------------------------------
__global__ void __launch_bounds__(128) sgconv_main_kernel(
    const float* __restrict__ x, const float* __restrict__ bias,
    float* __restrict__ out) {
    __shared__ float sH[7 * 5 * 16 * 16];   // 35840 B
    __shared__ float xT[132][20];           // 10560 B, rows 2..129 = t 0..127
    __shared__ float sb[16];

    const int tid = threadIdx.x;
    const int t   = tid;

    // load H (2240 float4, coalesced; L2-broadcast across blocks)
    {
        const float4* src = (const float4*)g_H;
        float4* dst = (float4*)sH;
        #pragma unroll
        for (int i = 0; i < 17; i++) dst[tid + i * 128] = src[tid + i * 128];
        int j = tid + 17 * 128;
        if (j < 2240) dst[j] = src[j];
    }
    // zero pads
    if (t < 2) {
        float4* p0 = (float4*)&xT[t][0];
        float4* p1 = (float4*)&xT[130 + t][0];
        float4 z = make_float4(0.f, 0.f, 0.f, 0.f);
        p0[0] = z; p0[1] = z; p0[2] = z; p0[3] = z;
        p1[0] = z; p1[1] = z; p1[2] = z; p1[3] = z;
    }
    if (tid < 16) sb[tid] = bias[tid];

    // load x row (coalesced float4)
    {
        const float4* xb = (const float4*)(x + (size_t)blockIdx.x * 2048 + t * 16);
        float4* dst = (float4*)&xT[t + 2][0];
        dst[0] = xb[0]; dst[1] = xb[1]; dst[2] = xb[2]; dst[3] = xb[3];
    }
    __syncthreads();   // the only barrier

    const int cls = (t <= 2) ? t : ((t >= 125) ? (t - 121) : 3);
    const float* Hc = sH + cls * 1280;

    float ov[16];
    #pragma unroll
    for (int qq = 0; qq < 4; qq++) {
        float4 b4 = ((const float4*)sb)[qq];
        ov[4*qq+0] = b4.x; ov[4*qq+1] = b4.y; ov[4*qq+2] = b4.z; ov[4*qq+3] = b4.w;
    }

    #pragma unroll
    for (int dt = 0; dt < 5; dt++) {
        const float4* xr = (const float4*)&xT[t + dt][0];
        float4 x0 = xr[0], x1 = xr[1], x2 = xr[2], x3 = xr[3];
        float xw[16] = { x0.x, x0.y, x0.z, x0.w,  x1.x, x1.y, x1.z, x1.w,
                         x2.x, x2.y, x2.z, x2.w,  x3.x, x3.y, x3.z, x3.w };
        const float* Hd = Hc + dt * 256;
        #pragma unroll
        for (int f = 0; f < 16; f++) {
            float a = xw[f];
            const float4* hr = (const float4*)(Hd + f * 16);
            float4 h0 = hr[0], h1 = hr[1], h2 = hr[2], h3 = hr[3];
            ov[0]  += a * h0.x;  ov[1]  += a * h0.y;  ov[2]  += a * h0.z;  ov[3]  += a * h0.w;
            ov[4]  += a * h1.x;  ov[5]  += a * h1.y;  ov[6]  += a * h1.z;  ov[7]  += a * h1.w;
            ov[8]  += a * h2.x;  ov[9]  += a * h2.y;  ov[10] += a * h2.z;  ov[11] += a * h2.w;
            ov[12] += a * h3.x;  ov[13] += a * h3.y;  ov[14] += a * h3.z;  ov[15] += a * h3.w;
        }
    }

    float4* ob = (float4*)(out + (size_t)blockIdx.x * 2048 + t * 16);
    ob[0] = make_float4(ov[0],  ov[1],  ov[2],  ov[3]);
    ob[1] = make_float4(ov[4],  ov[5],  ov[6],  ov[7]);
    ob[2] = make_float4(ov[8],  ov[9],  ov[10], ov[11]);
    ob[3] = make_float4(ov[12], ov[13], ov[14], ov[15]);
}

extern "C" void kernel_launch(void* const* d_in, const int* in_sizes, int n_in,
                              void* d_out, int out_size) {
    const float* x      = (const float*)d_in[0];  // [1024,128,16]
    const float* weight = (const float*)d_in[1];  // [3,16,16]
    const float* bias   = (const float*)d_in[2];  // [16]
    const float* adj    = (const float*)d_in[3];  // [16,16]
    int batch = in_sizes[0] / (T_LEN * F_DIM);

    setup_analytic_kernel<<<1, 128>>>(adj);
    build_H_kernel<<<1, 512>>>(weight);
    sgconv_main_kernel<<<batch, 128>>>(x, bias, (float*)d_out);
}